// round 2
// baseline (speedup 1.0000x reference)
#include <cuda_runtime.h>
#include <cstdint>
#include <cstddef>

// Flash attention, B=4 H=16 S=2048 D=64, fp32 in/out, tf32 mma.sync compute.
// scores = (Q K^T)/8 ; softmax ; out = P V.

#define LOG2E 1.4426950408889634f

constexpr int Bb = 4, Hh = 16, Ss = 2048, Dd = 64;
constexpr int BM = 64;   // query rows per CTA
constexpr int BN = 64;   // key rows per iteration
constexpr int SKW = 72;  // smem row stride in 32-bit words (64 + 8 pad)

__device__ __forceinline__ uint32_t f2tf(float x) {
    uint32_t r;
    asm("cvt.rna.tf32.f32 %0, %1;" : "=r"(r) : "f"(x));
    return r;
}

__device__ __forceinline__ void mma_tf32(float c[4], const uint32_t a[4],
                                         uint32_t b0, uint32_t b1) {
    asm volatile(
        "mma.sync.aligned.m16n8k8.row.col.f32.tf32.tf32.f32 "
        "{%0,%1,%2,%3}, {%4,%5,%6,%7}, {%8,%9}, {%0,%1,%2,%3};"
        : "+f"(c[0]), "+f"(c[1]), "+f"(c[2]), "+f"(c[3])
        : "r"(a[0]), "r"(a[1]), "r"(a[2]), "r"(a[3]), "r"(b0), "r"(b1));
}

__global__ __launch_bounds__(128) void fattn_tf32(
    const float* __restrict__ Q, const float* __restrict__ K,
    const float* __restrict__ V, float* __restrict__ O) {
    // sKP holds K tile during QK, then is reused for P (K dead after QK).
    __shared__ uint32_t sKP[BM * SKW];
    __shared__ uint32_t sV[BN * SKW];

    const int tid = threadIdx.x;
    const int warp = tid >> 5, lane = tid & 31;
    const int qg = lane >> 2;   // group id   (row within fragment)
    const int tg = lane & 3;    // thread-in-group (col within fragment)
    const int bh = blockIdx.y;
    const int m_blk = blockIdx.x * BM;

    const float* qp = Q + (size_t)bh * Ss * Dd;
    const float* kp = K + (size_t)bh * Ss * Dd;
    const float* vp = V + (size_t)bh * Ss * Dd;
    float* op = O + (size_t)bh * Ss * Dd;

    // ---- Q fragments in registers, pre-scaled by 1/8 (exact in tf32) ----
    uint32_t aQ[8][4];
    {
        const int r0 = m_blk + warp * 16 + qg;
        #pragma unroll
        for (int k = 0; k < 8; k++) {
            const int c0 = k * 8 + tg;
            aQ[k][0] = f2tf(qp[(size_t)r0 * Dd + c0] * 0.125f);
            aQ[k][1] = f2tf(qp[(size_t)(r0 + 8) * Dd + c0] * 0.125f);
            aQ[k][2] = f2tf(qp[(size_t)r0 * Dd + c0 + 4] * 0.125f);
            aQ[k][3] = f2tf(qp[(size_t)(r0 + 8) * Dd + c0 + 4] * 0.125f);
        }
    }

    float Oc[8][4];
    #pragma unroll
    for (int n = 0; n < 8; n++)
        #pragma unroll
        for (int j = 0; j < 4; j++) Oc[n][j] = 0.f;
    float mrow0 = -1e30f, mrow1 = -1e30f;
    float lrow0 = 0.f, lrow1 = 0.f;

    const int ldr = tid / 16;         // load row base (0..7)
    const int ldc = (tid % 16) * 4;   // load col (float4)

    for (int kb = 0; kb < Ss / BN; kb++) {
        __syncthreads();  // prior iteration's P/V reads complete

        // ---- stage K,V tiles (fp32 -> tf32 on store) ----
        const float* kg = kp + (size_t)kb * BN * Dd;
        const float* vg = vp + (size_t)kb * BN * Dd;
        #pragma unroll
        for (int rr = 0; rr < 8; rr++) {
            const int r = ldr + rr * 8;
            float4 kf = *(const float4*)(kg + r * Dd + ldc);
            float4 vf = *(const float4*)(vg + r * Dd + ldc);
            uint4 ku = make_uint4(f2tf(kf.x), f2tf(kf.y), f2tf(kf.z), f2tf(kf.w));
            uint4 vu = make_uint4(f2tf(vf.x), f2tf(vf.y), f2tf(vf.z), f2tf(vf.w));
            *(uint4*)(sKP + r * SKW + ldc) = ku;
            *(uint4*)(sV + r * SKW + ldc) = vu;
        }
        __syncthreads();

        // ---- S = (Q/8) K^T ----
        float sc[8][4];
        #pragma unroll
        for (int n = 0; n < 8; n++) {
            sc[n][0] = sc[n][1] = sc[n][2] = sc[n][3] = 0.f;
        }
        #pragma unroll
        for (int k = 0; k < 8; k++) {
            #pragma unroll
            for (int n = 0; n < 8; n++) {
                // B elem (d, key): K[key][d]
                uint32_t b0 = sKP[(n * 8 + qg) * SKW + k * 8 + tg];
                uint32_t b1 = sKP[(n * 8 + qg) * SKW + k * 8 + tg + 4];
                mma_tf32(sc[n], aQ[k], b0, b1);
            }
        }
        __syncthreads();  // all warps done reading K before P overwrite

        // ---- online softmax (two row-halves per thread) ----
        float mx0 = sc[0][0], mx1 = sc[0][2];
        #pragma unroll
        for (int n = 0; n < 8; n++) {
            mx0 = fmaxf(mx0, fmaxf(sc[n][0], sc[n][1]));
            mx1 = fmaxf(mx1, fmaxf(sc[n][2], sc[n][3]));
        }
        #pragma unroll
        for (int h = 1; h < 4; h <<= 1) {
            mx0 = fmaxf(mx0, __shfl_xor_sync(0xffffffffu, mx0, h));
            mx1 = fmaxf(mx1, __shfl_xor_sync(0xffffffffu, mx1, h));
        }
        const float mn0 = fmaxf(mrow0, mx0);
        const float mn1 = fmaxf(mrow1, mx1);
        const float al0 = exp2f((mrow0 - mn0) * LOG2E);
        const float al1 = exp2f((mrow1 - mn1) * LOG2E);
        mrow0 = mn0;
        mrow1 = mn1;
        float rs0 = 0.f, rs1 = 0.f;
        #pragma unroll
        for (int n = 0; n < 8; n++) {
            sc[n][0] = exp2f((sc[n][0] - mn0) * LOG2E);
            sc[n][1] = exp2f((sc[n][1] - mn0) * LOG2E);
            sc[n][2] = exp2f((sc[n][2] - mn1) * LOG2E);
            sc[n][3] = exp2f((sc[n][3] - mn1) * LOG2E);
            rs0 += sc[n][0] + sc[n][1];
            rs1 += sc[n][2] + sc[n][3];
            Oc[n][0] *= al0;
            Oc[n][1] *= al0;
            Oc[n][2] *= al1;
            Oc[n][3] *= al1;
        }
        lrow0 = lrow0 * al0 + rs0;  // per-lane partial; quad-reduced at end
        lrow1 = lrow1 * al1 + rs1;

        // ---- store P (tf32) into sKP; each warp touches only its 16 rows ----
        const int prow0 = warp * 16 + qg;
        #pragma unroll
        for (int n = 0; n < 8; n++) {
            sKP[prow0 * SKW + n * 8 + 2 * tg]       = f2tf(sc[n][0]);
            sKP[prow0 * SKW + n * 8 + 2 * tg + 1]   = f2tf(sc[n][1]);
            sKP[(prow0 + 8) * SKW + n * 8 + 2 * tg]     = f2tf(sc[n][2]);
            sKP[(prow0 + 8) * SKW + n * 8 + 2 * tg + 1] = f2tf(sc[n][3]);
        }
        __syncwarp();

        // ---- O += P V ----
        #pragma unroll
        for (int k = 0; k < 8; k++) {
            uint32_t aP[4];
            aP[0] = sKP[prow0 * SKW + k * 8 + tg];
            aP[1] = sKP[(prow0 + 8) * SKW + k * 8 + tg];
            aP[2] = sKP[prow0 * SKW + k * 8 + tg + 4];
            aP[3] = sKP[(prow0 + 8) * SKW + k * 8 + tg + 4];
            #pragma unroll
            for (int n = 0; n < 8; n++) {
                // B elem (key, d): V[key][d]
                uint32_t b0 = sV[(k * 8 + tg) * SKW + n * 8 + qg];
                uint32_t b1 = sV[(k * 8 + tg + 4) * SKW + n * 8 + qg];
                mma_tf32(Oc[n], aP, b0, b1);
            }
        }
    }

    // ---- epilogue: finish l reduction, normalize, write ----
    #pragma unroll
    for (int h = 1; h < 4; h <<= 1) {
        lrow0 += __shfl_xor_sync(0xffffffffu, lrow0, h);
        lrow1 += __shfl_xor_sync(0xffffffffu, lrow1, h);
    }
    const float inv0 = 1.f / lrow0;
    const float inv1 = 1.f / lrow1;
    const int r0 = m_blk + warp * 16 + qg;
    #pragma unroll
    for (int n = 0; n < 8; n++) {
        op[(size_t)r0 * Dd + n * 8 + 2 * tg]       = Oc[n][0] * inv0;
        op[(size_t)r0 * Dd + n * 8 + 2 * tg + 1]   = Oc[n][1] * inv0;
        op[(size_t)(r0 + 8) * Dd + n * 8 + 2 * tg]     = Oc[n][2] * inv1;
        op[(size_t)(r0 + 8) * Dd + n * 8 + 2 * tg + 1] = Oc[n][3] * inv1;
    }
}

extern "C" void kernel_launch(void* const* d_in, const int* in_sizes, int n_in,
                              void* d_out, int out_size) {
    const float* Q = (const float*)d_in[0];
    const float* K = (const float*)d_in[1];
    const float* V = (const float*)d_in[2];
    float* O = (float*)d_out;
    dim3 grid(Ss / BM, Bb * Hh);
    fattn_tf32<<<grid, 128>>>(Q, K, V, O);
}

// round 4
// speedup vs baseline: 1.1791x; 1.1791x over previous
#include <cuda_runtime.h>
#include <cstdint>
#include <cstddef>

// Flash attention, B=4 H=16 S=2048 D=64, fp32 in/out, tf32 mma.sync compute.
// scores = (Q K^T)/8 ; softmax ; out = P V.
// R3: conflict-free smem strides + ldmatrix fragment loads.

#define LOG2E 1.4426950408889634f

constexpr int Bb = 4, Hh = 16, Ss = 2048, Dd = 64;
constexpr int BM = 64;   // query rows per CTA
constexpr int BN = 64;   // key rows per iteration
constexpr int KW = 68;   // sKP stride words (row stride = 4 banks -> conflict-free QK/aP)
constexpr int VW = 72;   // sV  stride words (row stride = 8 banks -> conflict-free PV)

__device__ __forceinline__ uint32_t f2tf(float x) {
    uint32_t r;
    asm("cvt.rna.tf32.f32 %0, %1;" : "=r"(r) : "f"(x));
    return r;
}

__device__ __forceinline__ void mma_tf32(float c[4], uint32_t a0, uint32_t a1,
                                         uint32_t a2, uint32_t a3,
                                         uint32_t b0, uint32_t b1) {
    asm volatile(
        "mma.sync.aligned.m16n8k8.row.col.f32.tf32.tf32.f32 "
        "{%0,%1,%2,%3}, {%4,%5,%6,%7}, {%8,%9}, {%0,%1,%2,%3};"
        : "+f"(c[0]), "+f"(c[1]), "+f"(c[2]), "+f"(c[3])
        : "r"(a0), "r"(a1), "r"(a2), "r"(a3), "r"(b0), "r"(b1));
}

__device__ __forceinline__ void ldsm4(uint32_t& r0, uint32_t& r1, uint32_t& r2,
                                      uint32_t& r3, uint32_t addr) {
    asm volatile(
        "ldmatrix.sync.aligned.m8n8.x4.shared.b16 {%0,%1,%2,%3}, [%4];"
        : "=r"(r0), "=r"(r1), "=r"(r2), "=r"(r3)
        : "r"(addr));
}

__global__ __launch_bounds__(128, 4) void fattn_tf32(
    const float* __restrict__ Q, const float* __restrict__ K,
    const float* __restrict__ V, float* __restrict__ O) {
    // sKP holds K tile during QK, then is reused for P (K dead after QK).
    __shared__ uint32_t sKP[BM * KW];
    __shared__ uint32_t sV[BN * VW];

    const int tid = threadIdx.x;
    const int warp = tid >> 5, lane = tid & 31;
    const int qg = lane >> 2;   // fragment row group
    const int tg = lane & 3;    // thread-in-group
    const int bh = blockIdx.y;
    const int m_blk = blockIdx.x * BM;

    const float* qp = Q + (size_t)bh * Ss * Dd;
    const float* kp = K + (size_t)bh * Ss * Dd;
    const float* vp = V + (size_t)bh * Ss * Dd;
    float* op = O + (size_t)bh * Ss * Dd;

    // ---- ldmatrix lane geometry ----
    // m = lane>>3 selects (row-group bit1, col-half bit0); rr = row within matrix.
    const int lm_m = lane >> 3, lm_r = lane & 7;
    const uint32_t skp_base = (uint32_t)__cvta_generic_to_shared(sKP);
    // QK B: matrices (nb=2p + (m>>1), half=m&1), rows = keys.
    uint32_t qk_addr[4];
#pragma unroll
    for (int p = 0; p < 4; p++) {
        const int krow = (2 * p + (lm_m >> 1)) * 8 + lm_r;
        qk_addr[p] = skp_base + (uint32_t)((krow * KW + (lm_m & 1) * 4) * 4);
    }
    // aP: A fragment of this warp's 16 P rows.
    const uint32_t ap_addr =
        skp_base +
        (uint32_t)(((warp * 16 + (lm_m >> 1) * 8 + lm_r) * KW + (lm_m & 1) * 4) * 4);

    // ---- Q fragments, pre-scaled by 1/8 (exact in tf32) ----
    uint32_t aQ[8][4];
    {
        const int r0 = m_blk + warp * 16 + qg;
#pragma unroll
        for (int k = 0; k < 8; k++) {
            const int c0 = k * 8 + tg;
            aQ[k][0] = f2tf(qp[(size_t)r0 * Dd + c0] * 0.125f);
            aQ[k][1] = f2tf(qp[(size_t)(r0 + 8) * Dd + c0] * 0.125f);
            aQ[k][2] = f2tf(qp[(size_t)r0 * Dd + c0 + 4] * 0.125f);
            aQ[k][3] = f2tf(qp[(size_t)(r0 + 8) * Dd + c0 + 4] * 0.125f);
        }
    }

    float Oc[8][4];
#pragma unroll
    for (int n = 0; n < 8; n++)
#pragma unroll
        for (int j = 0; j < 4; j++) Oc[n][j] = 0.f;
    float mrow0 = -1e30f, mrow1 = -1e30f;
    float lrow0 = 0.f, lrow1 = 0.f;

    const int ldr = tid / 16;         // staging row base
    const int ldc = (tid % 16) * 4;   // staging col (float4)

    for (int kb = 0; kb < Ss / BN; kb++) {
        __syncthreads();  // prior iteration's P/V reads complete

        // ---- stage K,V tiles (fp32 -> tf32 on store) ----
        const float* kg = kp + (size_t)kb * BN * Dd;
        const float* vg = vp + (size_t)kb * BN * Dd;
#pragma unroll
        for (int rr = 0; rr < 8; rr++) {
            const int r = ldr + rr * 8;
            float4 kf = *(const float4*)(kg + r * Dd + ldc);
            float4 vf = *(const float4*)(vg + r * Dd + ldc);
            uint4 ku = make_uint4(f2tf(kf.x), f2tf(kf.y), f2tf(kf.z), f2tf(kf.w));
            uint4 vu = make_uint4(f2tf(vf.x), f2tf(vf.y), f2tf(vf.z), f2tf(vf.w));
            *(uint4*)(sKP + r * KW + ldc) = ku;
            *(uint4*)(sV + r * VW + ldc) = vu;
        }
        __syncthreads();

        // ---- S = (Q/8) K^T : B fragments via ldmatrix ----
        float sc[8][4];
#pragma unroll
        for (int n = 0; n < 8; n++)
            sc[n][0] = sc[n][1] = sc[n][2] = sc[n][3] = 0.f;
#pragma unroll
        for (int k = 0; k < 8; k++) {
#pragma unroll
            for (int p = 0; p < 4; p++) {
                uint32_t b0, b1, b2, b3;
                ldsm4(b0, b1, b2, b3, qk_addr[p] + (uint32_t)(k * 32));
                mma_tf32(sc[2 * p], aQ[k][0], aQ[k][1], aQ[k][2], aQ[k][3], b0, b1);
                mma_tf32(sc[2 * p + 1], aQ[k][0], aQ[k][1], aQ[k][2], aQ[k][3], b2, b3);
            }
        }
        __syncthreads();  // all warps done reading K before P overwrite

        // ---- online softmax (two row-halves per thread) ----
        float mx0 = sc[0][0], mx1 = sc[0][2];
#pragma unroll
        for (int n = 0; n < 8; n++) {
            mx0 = fmaxf(mx0, fmaxf(sc[n][0], sc[n][1]));
            mx1 = fmaxf(mx1, fmaxf(sc[n][2], sc[n][3]));
        }
#pragma unroll
        for (int h = 1; h < 4; h <<= 1) {
            mx0 = fmaxf(mx0, __shfl_xor_sync(0xffffffffu, mx0, h));
            mx1 = fmaxf(mx1, __shfl_xor_sync(0xffffffffu, mx1, h));
        }
        const float mn0 = fmaxf(mrow0, mx0);
        const float mn1 = fmaxf(mrow1, mx1);
        const float al0 = exp2f((mrow0 - mn0) * LOG2E);
        const float al1 = exp2f((mrow1 - mn1) * LOG2E);
        mrow0 = mn0;
        mrow1 = mn1;
        float rs0 = 0.f, rs1 = 0.f;
#pragma unroll
        for (int n = 0; n < 8; n++) {
            sc[n][0] = exp2f((sc[n][0] - mn0) * LOG2E);
            sc[n][1] = exp2f((sc[n][1] - mn0) * LOG2E);
            sc[n][2] = exp2f((sc[n][2] - mn1) * LOG2E);
            sc[n][3] = exp2f((sc[n][3] - mn1) * LOG2E);
            rs0 += sc[n][0] + sc[n][1];
            rs1 += sc[n][2] + sc[n][3];
            Oc[n][0] *= al0;
            Oc[n][1] *= al0;
            Oc[n][2] *= al1;
            Oc[n][3] *= al1;
        }
        lrow0 = lrow0 * al0 + rs0;  // per-lane partial; quad-reduced at end
        lrow1 = lrow1 * al1 + rs1;

        // ---- store P (tf32) into sKP; each warp touches only its 16 rows ----
        const int prow0 = warp * 16 + qg;
        uint32_t* pr0 = sKP + prow0 * KW + 2 * tg;
        uint32_t* pr1 = sKP + (prow0 + 8) * KW + 2 * tg;
#pragma unroll
        for (int n = 0; n < 8; n++) {
            uint2 lo = make_uint2(f2tf(sc[n][0]), f2tf(sc[n][1]));
            uint2 hi = make_uint2(f2tf(sc[n][2]), f2tf(sc[n][3]));
            *(uint2*)(pr0 + n * 8) = lo;
            *(uint2*)(pr1 + n * 8) = hi;
        }
        __syncwarp();

        // ---- O += P V : aP via ldmatrix, V fragments scalar (conflict-free) ----
        const uint32_t* vb = sV + tg * VW + qg;
#pragma unroll
        for (int k = 0; k < 8; k++) {
            uint32_t p0, p1, p2, p3;
            ldsm4(p0, p1, p2, p3, ap_addr + (uint32_t)(k * 32));
            // {r0,r1,r2,r3} = {a0,a2,a1,a3}
#pragma unroll
            for (int n = 0; n < 8; n++) {
                uint32_t b0 = vb[k * 8 * VW + n * 8];
                uint32_t b1 = vb[(k * 8 + 4) * VW + n * 8];
                mma_tf32(Oc[n], p0, p2, p1, p3, b0, b1);
            }
        }
    }

    // ---- epilogue: finish l reduction, normalize, write ----
#pragma unroll
    for (int h = 1; h < 4; h <<= 1) {
        lrow0 += __shfl_xor_sync(0xffffffffu, lrow0, h);
        lrow1 += __shfl_xor_sync(0xffffffffu, lrow1, h);
    }
    const float inv0 = 1.f / lrow0;
    const float inv1 = 1.f / lrow1;
    const int r0 = m_blk + warp * 16 + qg;
#pragma unroll
    for (int n = 0; n < 8; n++) {
        op[(size_t)r0 * Dd + n * 8 + 2 * tg]       = Oc[n][0] * inv0;
        op[(size_t)r0 * Dd + n * 8 + 2 * tg + 1]   = Oc[n][1] * inv0;
        op[(size_t)(r0 + 8) * Dd + n * 8 + 2 * tg]     = Oc[n][2] * inv1;
        op[(size_t)(r0 + 8) * Dd + n * 8 + 2 * tg + 1] = Oc[n][3] * inv1;
    }
}

extern "C" void kernel_launch(void* const* d_in, const int* in_sizes, int n_in,
                              void* d_out, int out_size) {
    const float* Q = (const float*)d_in[0];
    const float* K = (const float*)d_in[1];
    const float* V = (const float*)d_in[2];
    float* O = (float*)d_out;
    dim3 grid(Ss / BM, Bb * Hh);
    fattn_tf32<<<grid, 128>>>(Q, K, V, O);
}